// round 1
// baseline (speedup 1.0000x reference)
#include <cuda_runtime.h>
#include <cuda_bf16.h>

// Problem dims
#define BATCH 8
#define NPTS  4096
#define MROWS (BATCH * NPTS)   // 32768
#define FDIM  512
#define NCOL  512
#define KDIM  512

// GEMM tiling
#define BM 128
#define BN 128
#define BK 16
#define TM 8
#define TN 8
#define GEMM_THREADS 256

// ---------------------------------------------------------------------------
// Scratch (device globals — no dynamic allocation allowed)
// ---------------------------------------------------------------------------
__device__ float g_feat[MROWS * 12];
__device__ float g_h [MROWS * FDIM];
__device__ float g_h2[MROWS * FDIM];
__device__ float g_std1[MROWS];
__device__ float g_std2[MROWS];

// ---------------------------------------------------------------------------
// Kernel 1: nearest-neighbor + local covariance features.
// rp layout: [B, 3, N]. For each point i: n0 = self, n1 = argmax_j!=i of
// pd = 2*dot(pi,pj) - |pi|^2 - |pj|^2   (negative squared distance),
// tie-break: smallest j (matches jax.lax.top_k ordering).
// feat[i, 0:3] = p_i ; feat[i, 3+3a+b] = p_i[a] * p_j[b]
// ---------------------------------------------------------------------------
__global__ __launch_bounds__(256) void knn_feat_kernel(
    const float* __restrict__ rp, float* __restrict__ feat)
{
    __shared__ float px[NPTS];
    __shared__ float py[NPTS];
    __shared__ float pz[NPTS];

    const int b = blockIdx.y;
    const float* base = rp + b * 3 * NPTS;
    for (int i = threadIdx.x; i < NPTS; i += 256) {
        px[i] = base[i];
        py[i] = base[NPTS + i];
        pz[i] = base[2 * NPTS + i];
    }
    __syncthreads();

    const int n = blockIdx.x * 256 + threadIdx.x;
    const float xi = px[n], yi = py[n], zi = pz[n];
    const float xxi = xi * xi + yi * yi + zi * zi;

    float bestv = -1e30f;
    int bestj = 0;
    for (int j = 0; j < NPTS; j++) {
        const float xj = px[j], yj = py[j], zj = pz[j];
        const float d = 2.0f * (xi * xj + yi * yj + zi * zj)
                        - xxi - (xj * xj + yj * yj + zj * zj);
        if (j != n && d > bestv) { bestv = d; bestj = j; }
    }

    const float nx = px[bestj], ny = py[bestj], nz = pz[bestj];
    float* f = feat + (b * NPTS + n) * 12;
    f[0] = xi;      f[1] = yi;      f[2] = zi;
    f[3] = xi * nx; f[4] = xi * ny; f[5] = xi * nz;
    f[6] = yi * nx; f[7] = yi * ny; f[8] = yi * nz;
    f[9] = zi * nx; f[10] = zi * ny; f[11] = zi * nz;
}

// ---------------------------------------------------------------------------
// Kernel 2: fp32 tiled GEMM with fused concat-tail, residual add, bias, ReLU.
//   C[M,512] = relu( A[M,512] @ W[0:512, :] + A2[M,K2] @ W[512:512+K2, :]
//                    + bias + (addsrc ? addsrc : 0) )
// 128x128x16 tile, 8x8 per thread, register-prefetch double pipeline.
// ---------------------------------------------------------------------------
__global__ __launch_bounds__(GEMM_THREADS) void gemm_fused_kernel(
    const float* __restrict__ A,
    const float* __restrict__ A2, const int K2,
    const float* __restrict__ W,
    const float* __restrict__ bias,
    const float* __restrict__ addsrc,
    float* __restrict__ C)
{
    __shared__ float As[BK][BM + 4];
    __shared__ float Bs[BK][BN];

    const int tid = threadIdx.x;
    const int m0 = blockIdx.y * BM;
    const int n0 = blockIdx.x * BN;

    const int tm0 = (tid >> 4) * TM;   // 0..120
    const int tn0 = (tid & 15) * TN;   // 0..120

    // A-tile loader: 2 float4 per thread; item id -> row = id/4, colgroup = id%4
    const int ar0 = tid >> 2;          // 0..63 (second item: +64)
    const int acg = tid & 3;
    // B-tile loader: 2 float4 per thread; item id -> kk = id/32, c4 = id%32
    const int bk0 = tid >> 5;          // 0..7 (second item: +8)
    const int bc4 = tid & 31;

    float acc[TM][TN];
    #pragma unroll
    for (int i = 0; i < TM; i++)
        #pragma unroll
        for (int j = 0; j < TN; j++) acc[i][j] = 0.0f;

    const float* Aptr = A + m0 * KDIM;

    float4 pa0, pa1, pb0, pb1;
    pa0 = *(const float4*)(Aptr + ar0 * KDIM + acg * 4);
    pa1 = *(const float4*)(Aptr + (ar0 + 64) * KDIM + acg * 4);
    pb0 = *(const float4*)(W + bk0 * NCOL + n0 + bc4 * 4);
    pb1 = *(const float4*)(W + (bk0 + 8) * NCOL + n0 + bc4 * 4);

    for (int kt = 0; kt < KDIM; kt += BK) {
        // store prefetched tile to smem (A transposed with pad)
        As[acg * 4 + 0][ar0] = pa0.x;
        As[acg * 4 + 1][ar0] = pa0.y;
        As[acg * 4 + 2][ar0] = pa0.z;
        As[acg * 4 + 3][ar0] = pa0.w;
        As[acg * 4 + 0][ar0 + 64] = pa1.x;
        As[acg * 4 + 1][ar0 + 64] = pa1.y;
        As[acg * 4 + 2][ar0 + 64] = pa1.z;
        As[acg * 4 + 3][ar0 + 64] = pa1.w;
        *(float4*)&Bs[bk0][bc4 * 4]     = pb0;
        *(float4*)&Bs[bk0 + 8][bc4 * 4] = pb1;
        __syncthreads();

        // prefetch next tile into registers
        if (kt + BK < KDIM) {
            const int kn = kt + BK;
            pa0 = *(const float4*)(Aptr + ar0 * KDIM + kn + acg * 4);
            pa1 = *(const float4*)(Aptr + (ar0 + 64) * KDIM + kn + acg * 4);
            pb0 = *(const float4*)(W + (kn + bk0) * NCOL + n0 + bc4 * 4);
            pb1 = *(const float4*)(W + (kn + bk0 + 8) * NCOL + n0 + bc4 * 4);
        }

        // compute
        #pragma unroll
        for (int k = 0; k < BK; k++) {
            float a[TM], bv[TN];
            *(float4*)&a[0]  = *(const float4*)&As[k][tm0];
            *(float4*)&a[4]  = *(const float4*)&As[k][tm0 + 4];
            *(float4*)&bv[0] = *(const float4*)&Bs[k][tn0];
            *(float4*)&bv[4] = *(const float4*)&Bs[k][tn0 + 4];
            #pragma unroll
            for (int i = 0; i < TM; i++)
                #pragma unroll
                for (int j = 0; j < TN; j++)
                    acc[i][j] += a[i] * bv[j];
        }
        __syncthreads();
    }

    // K-tail: A2[M,K2] @ W[512 : 512+K2, :]
    for (int kk = 0; kk < K2; kk++) {
        float wv[TN];
        #pragma unroll
        for (int j = 0; j < TN; j++)
            wv[j] = W[(KDIM + kk) * NCOL + n0 + tn0 + j];
        #pragma unroll
        for (int i = 0; i < TM; i++) {
            const float a2v = A2[(m0 + tm0 + i) * K2 + kk];
            #pragma unroll
            for (int j = 0; j < TN; j++)
                acc[i][j] += a2v * wv[j];
        }
    }

    // epilogue: (+addsrc) + bias, relu, store
    float bvals[TN];
    *(float4*)&bvals[0] = *(const float4*)(bias + n0 + tn0);
    *(float4*)&bvals[4] = *(const float4*)(bias + n0 + tn0 + 4);

    #pragma unroll
    for (int i = 0; i < TM; i++) {
        const int row = m0 + tm0 + i;
        float v[TN];
        #pragma unroll
        for (int j = 0; j < TN; j++) v[j] = acc[i][j] + bvals[j];
        if (addsrc != nullptr) {
            float4 r0 = *(const float4*)(addsrc + row * NCOL + n0 + tn0);
            float4 r1 = *(const float4*)(addsrc + row * NCOL + n0 + tn0 + 4);
            v[0] += r0.x; v[1] += r0.y; v[2] += r0.z; v[3] += r0.w;
            v[4] += r1.x; v[5] += r1.y; v[6] += r1.z; v[7] += r1.w;
        }
        #pragma unroll
        for (int j = 0; j < TN; j++) v[j] = fmaxf(v[j], 0.0f);
        *(float4*)(C + row * NCOL + n0 + tn0)     = *(float4*)&v[0];
        *(float4*)(C + row * NCOL + n0 + tn0 + 4) = *(float4*)&v[4];
    }
}

// ---------------------------------------------------------------------------
// Kernel 3: per-row dot with w2 (+b2), plus cross-stage residual accumulation.
// out[row] = (prev ? prev[row] : 0) + dot(H[row,:], w2) + b2[0]
// One warp per row.
// ---------------------------------------------------------------------------
__global__ __launch_bounds__(256) void rowdot_kernel(
    const float* __restrict__ H,
    const float* __restrict__ w2,
    const float* __restrict__ b2,
    const float* __restrict__ prev,
    float* __restrict__ out)
{
    const int warp = threadIdx.x >> 5;
    const int lane = threadIdx.x & 31;
    const int row = blockIdx.x * 8 + warp;

    const float4* hp = (const float4*)(H + row * NCOL);
    const float4* wp = (const float4*)w2;

    float s = 0.0f;
    #pragma unroll
    for (int q = 0; q < 4; q++) {
        const float4 h4 = hp[lane + 32 * q];
        const float4 w4 = wp[lane + 32 * q];
        s += h4.x * w4.x + h4.y * w4.y + h4.z * w4.z + h4.w * w4.w;
    }
    #pragma unroll
    for (int o = 16; o; o >>= 1) s += __shfl_xor_sync(0xFFFFFFFFu, s, o);

    if (lane == 0)
        out[row] = (prev ? prev[row] : 0.0f) + s + b2[0];
}

// ---------------------------------------------------------------------------
// Host orchestration
// ---------------------------------------------------------------------------
extern "C" void kernel_launch(void* const* d_in, const int* in_sizes, int n_in,
                              void* d_out, int out_size)
{
    const float* latent = (const float*)d_in[0];
    const float* rp     = (const float*)d_in[1];

    const float* s1_w1 = (const float*)d_in[2];
    const float* s1_b1 = (const float*)d_in[3];
    const float* s1_wr = (const float*)d_in[4];
    const float* s1_br = (const float*)d_in[5];
    const float* s1_w2 = (const float*)d_in[6];
    const float* s1_b2 = (const float*)d_in[7];

    const float* s2_w1 = (const float*)d_in[8];
    const float* s2_b1 = (const float*)d_in[9];
    const float* s2_wr = (const float*)d_in[10];
    const float* s2_br = (const float*)d_in[11];
    const float* s2_w2 = (const float*)d_in[12];
    const float* s2_b2 = (const float*)d_in[13];

    const float* s3_w1 = (const float*)d_in[14];
    const float* s3_b1 = (const float*)d_in[15];
    const float* s3_wr = (const float*)d_in[16];
    const float* s3_br = (const float*)d_in[17];
    const float* s3_w2 = (const float*)d_in[18];
    const float* s3_b2 = (const float*)d_in[19];

    float *feat, *h, *h2, *std1, *std2;
    cudaGetSymbolAddress((void**)&feat, g_feat);
    cudaGetSymbolAddress((void**)&h,    g_h);
    cudaGetSymbolAddress((void**)&h2,   g_h2);
    cudaGetSymbolAddress((void**)&std1, g_std1);
    cudaGetSymbolAddress((void**)&std2, g_std2);

    float* out = (float*)d_out;

    const dim3 gemm_grid(NCOL / BN, MROWS / BM);   // (4, 256)
    const int  rd_blocks = MROWS / 8;              // 4096

    // local covariance features
    knn_feat_kernel<<<dim3(NPTS / 256, BATCH), 256>>>(rp, feat);

    // ---- stage 1 ----
    gemm_fused_kernel<<<gemm_grid, GEMM_THREADS>>>(latent, feat, 12, s1_w1, s1_b1, nullptr, h);
    gemm_fused_kernel<<<gemm_grid, GEMM_THREADS>>>(h, nullptr, 0, s1_wr, s1_br, h, h2);
    rowdot_kernel<<<rd_blocks, 256>>>(h2, s1_w2, s1_b2, nullptr, std1);

    // ---- stage 2 ----
    gemm_fused_kernel<<<gemm_grid, GEMM_THREADS>>>(latent, std1, 1, s2_w1, s2_b1, nullptr, h);
    gemm_fused_kernel<<<gemm_grid, GEMM_THREADS>>>(h, nullptr, 0, s2_wr, s2_br, h, h2);
    rowdot_kernel<<<rd_blocks, 256>>>(h2, s2_w2, s2_b2, std1, std2);

    // ---- stage 3 ----
    gemm_fused_kernel<<<gemm_grid, GEMM_THREADS>>>(latent, std2, 1, s3_w1, s3_b1, nullptr, h);
    gemm_fused_kernel<<<gemm_grid, GEMM_THREADS>>>(h, nullptr, 0, s3_wr, s3_br, h, h2);
    rowdot_kernel<<<rd_blocks, 256>>>(h2, s3_w2, s3_b2, std2, out);
}

// round 3
// speedup vs baseline: 2.2370x; 2.2370x over previous
#include <cuda_runtime.h>
#include <cuda_bf16.h>
#include <cstdint>

#define BATCH 8
#define NPTS  4096
#define MROWS 32768
#define FD    512

// GEMM tiling
#define BM 128
#define BN 128
#define BK 32
#define LDA 40                    // halves per smem row (pad 8)
#define ARR_BYTES (BM * LDA * 2)  // 10240
#define STAGE_BYTES (4 * ARR_BYTES)
#define SMEM_TOTAL (2 * STAGE_BYTES)   // 81920

// ---------------------------------------------------------------------------
// Device scratch
// ---------------------------------------------------------------------------
__device__ float          g_feat[MROWS * 12];
__device__ __nv_bfloat16  g_lat_hi[MROWS * FD];
__device__ __nv_bfloat16  g_lat_lo[MROWS * FD];
__device__ __nv_bfloat16  g_h_hi[MROWS * FD];
__device__ __nv_bfloat16  g_h_lo[MROWS * FD];
__device__ float          g_h2[MROWS * FD];
__device__ float          g_std1[MROWS];
__device__ float          g_std2[MROWS];
__device__ __nv_bfloat16  g_w1T_hi[FD * FD];
__device__ __nv_bfloat16  g_w1T_lo[FD * FD];
__device__ __nv_bfloat16  g_wrT_hi[FD * FD];
__device__ __nv_bfloat16  g_wrT_lo[FD * FD];

// ---------------------------------------------------------------------------
// Helpers
// ---------------------------------------------------------------------------
__device__ __forceinline__ uint32_t smem_u32(const void* p) {
    uint32_t a;
    asm("{ .reg .u64 t; cvta.to.shared.u64 t, %1; cvt.u32.u64 %0, t; }" : "=r"(a) : "l"(p));
    return a;
}

__device__ __forceinline__ void cp16(uint32_t s, const void* g) {
    asm volatile("cp.async.cg.shared.global [%0], [%1], 16;" :: "r"(s), "l"(g));
}
__device__ __forceinline__ void cp_commit() { asm volatile("cp.async.commit_group;"); }
template <int N>
__device__ __forceinline__ void cp_wait() { asm volatile("cp.async.wait_group %0;" :: "n"(N)); }

__device__ __forceinline__ void ldmx4(uint32_t addr, uint32_t& r0, uint32_t& r1, uint32_t& r2, uint32_t& r3) {
    asm volatile("ldmatrix.sync.aligned.m8n8.x4.shared.b16 {%0,%1,%2,%3}, [%4];"
        : "=r"(r0), "=r"(r1), "=r"(r2), "=r"(r3) : "r"(addr));
}

__device__ __forceinline__ void mma_bf16(float* c, const uint32_t* a, const uint32_t* b) {
    asm volatile(
        "mma.sync.aligned.m16n8k16.row.col.f32.bf16.bf16.f32 "
        "{%0,%1,%2,%3}, {%4,%5,%6,%7}, {%8,%9}, {%0,%1,%2,%3};"
        : "+f"(c[0]), "+f"(c[1]), "+f"(c[2]), "+f"(c[3])
        : "r"(a[0]), "r"(a[1]), "r"(a[2]), "r"(a[3]), "r"(b[0]), "r"(b[1]));
}

__device__ __forceinline__ void split2(float x, __nv_bfloat16& h, __nv_bfloat16& l) {
    h = __float2bfloat16(x);
    l = __float2bfloat16(x - __bfloat162float(h));
}

// ---------------------------------------------------------------------------
// kNN + local covariance
// ---------------------------------------------------------------------------
__global__ __launch_bounds__(256) void knn_feat_kernel(
    const float* __restrict__ rp, float* __restrict__ feat)
{
    __shared__ float px[NPTS], py[NPTS], pz[NPTS];
    const int b = blockIdx.y;
    const float* base = rp + b * 3 * NPTS;
    for (int i = threadIdx.x; i < NPTS; i += 256) {
        px[i] = base[i]; py[i] = base[NPTS + i]; pz[i] = base[2 * NPTS + i];
    }
    __syncthreads();

    const int n = blockIdx.x * 256 + threadIdx.x;
    const float xi = px[n], yi = py[n], zi = pz[n];
    const float xxi = xi * xi + yi * yi + zi * zi;

    float bestv = -1e30f; int bestj = 0;
    for (int j = 0; j < NPTS; j++) {
        const float xj = px[j], yj = py[j], zj = pz[j];
        const float d = 2.0f * (xi * xj + yi * yj + zi * zj) - xxi - (xj * xj + yj * yj + zj * zj);
        if (j != n && d > bestv) { bestv = d; bestj = j; }
    }
    const float nx = px[bestj], ny = py[bestj], nz = pz[bestj];
    float* f = feat + (size_t)(b * NPTS + n) * 12;
    f[0] = xi;      f[1] = yi;      f[2] = zi;
    f[3] = xi * nx; f[4] = xi * ny; f[5] = xi * nz;
    f[6] = yi * nx; f[7] = yi * ny; f[8] = yi * nz;
    f[9] = zi * nx; f[10] = zi * ny; f[11] = zi * nz;
}

// ---------------------------------------------------------------------------
// fp32 -> bf16 hi/lo split (bulk)
// ---------------------------------------------------------------------------
__global__ __launch_bounds__(256) void conv_split_kernel(
    const float* __restrict__ x, __nv_bfloat16* __restrict__ hi,
    __nv_bfloat16* __restrict__ lo, int n4)
{
    for (int i = blockIdx.x * 256 + threadIdx.x; i < n4; i += gridDim.x * 256) {
        float4 v = ((const float4*)x)[i];
        __nv_bfloat16 h0,h1,h2,h3,l0,l1,l2,l3;
        split2(v.x,h0,l0); split2(v.y,h1,l1); split2(v.z,h2,l2); split2(v.w,h3,l3);
        __nv_bfloat162* ph = (__nv_bfloat162*)hi + i * 2;
        __nv_bfloat162* pl = (__nv_bfloat162*)lo + i * 2;
        ph[0] = __nv_bfloat162(h0, h1); ph[1] = __nv_bfloat162(h2, h3);
        pl[0] = __nv_bfloat162(l0, l1); pl[1] = __nv_bfloat162(l2, l3);
    }
}

// ---------------------------------------------------------------------------
// W[512,512] (k-major) -> WT[n][k] bf16 hi/lo
// ---------------------------------------------------------------------------
__global__ __launch_bounds__(256) void transW_kernel(
    const float* __restrict__ W, __nv_bfloat16* __restrict__ th, __nv_bfloat16* __restrict__ tl)
{
    __shared__ float t[32][33];
    const int n0 = blockIdx.x * 32, k0 = blockIdx.y * 32;
    const int tx = threadIdx.x & 31, ty = threadIdx.x >> 5;
    #pragma unroll
    for (int i = 0; i < 4; i++)
        t[ty + i * 8][tx] = W[(size_t)(k0 + ty + i * 8) * FD + n0 + tx];
    __syncthreads();
    #pragma unroll
    for (int i = 0; i < 4; i++) {
        float v = t[tx][ty + i * 8];
        __nv_bfloat16 h, l; split2(v, h, l);
        size_t o = (size_t)(n0 + ty + i * 8) * FD + k0 + tx;
        th[o] = h; tl[o] = l;
    }
}

// ---------------------------------------------------------------------------
// Split-bf16 mma.sync GEMM with fused tail / bias / residual / relu.
//   C[M, 512] = relu( A @ B^T (hi/lo split, fp32 acc)
//                     + A2[M,K2] @ Wtail + bias + (addres ? A : 0) )
// ---------------------------------------------------------------------------
__global__ __launch_bounds__(256) void gemm_mma_kernel(
    const __nv_bfloat16* __restrict__ Ahi, const __nv_bfloat16* __restrict__ Alo,
    const __nv_bfloat16* __restrict__ Bhi, const __nv_bfloat16* __restrict__ Blo,
    const float* __restrict__ bias,
    const float* __restrict__ A2, const int K2, const float* __restrict__ Wtail,
    const int addres,
    float* __restrict__ outF,
    __nv_bfloat16* __restrict__ outHi, __nv_bfloat16* __restrict__ outLo)
{
    extern __shared__ __align__(16) char dsm[];
    const uint32_t sbase = smem_u32(dsm);

    const int tid = threadIdx.x;
    const int m0 = blockIdx.y * BM;
    const int n0 = blockIdx.x * BN;
    const int warp = tid >> 5, lane = tid & 31;
    const int warp_m = warp >> 2;          // 0..1 -> 64 rows
    const int warp_n = warp & 3;           // 0..3 -> 32 cols

    // loader indices: id -> row = id>>2, kq = id&3 (16B each)
    const int lr0 = tid >> 2;              // 0..63  (also +64)
    const int lkq = tid & 3;

    // global row pointers for loads
    const size_t gA0 = (size_t)(m0 + lr0) * FD + lkq * 8;
    const size_t gA1 = (size_t)(m0 + lr0 + 64) * FD + lkq * 8;
    const size_t gB0 = (size_t)(n0 + lr0) * FD + lkq * 8;
    const size_t gB1 = (size_t)(n0 + lr0 + 64) * FD + lkq * 8;
    const uint32_t so0 = (uint32_t)(lr0 * LDA * 2 + lkq * 16);
    const uint32_t so1 = (uint32_t)((lr0 + 64) * LDA * 2 + lkq * 16);

    auto issue = [&](int chunk) {
        const int kc = chunk * BK;
        const uint32_t st = sbase + (chunk & 1) * STAGE_BYTES;
        cp16(st + 0 * ARR_BYTES + so0, Ahi + gA0 + kc);
        cp16(st + 0 * ARR_BYTES + so1, Ahi + gA1 + kc);
        cp16(st + 1 * ARR_BYTES + so0, Alo + gA0 + kc);
        cp16(st + 1 * ARR_BYTES + so1, Alo + gA1 + kc);
        cp16(st + 2 * ARR_BYTES + so0, Bhi + gB0 + kc);
        cp16(st + 2 * ARR_BYTES + so1, Bhi + gB1 + kc);
        cp16(st + 3 * ARR_BYTES + so0, Blo + gB0 + kc);
        cp16(st + 3 * ARR_BYTES + so1, Blo + gB1 + kc);
        cp_commit();
    };

    float c[4][4][4];
    #pragma unroll
    for (int i = 0; i < 4; i++)
        #pragma unroll
        for (int j = 0; j < 4; j++)
            #pragma unroll
            for (int q = 0; q < 4; q++) c[i][j][q] = 0.0f;

    issue(0);

    const int arow = (lane & 15);
    const int acolb = (lane >> 4) * 16;    // byte offset within k16 block

    #pragma unroll 1
    for (int ch = 0; ch < FD / BK; ch++) {
        if (ch + 1 < FD / BK) { issue(ch + 1); cp_wait<1>(); }
        else                  { cp_wait<0>(); }
        __syncthreads();

        const uint32_t st = sbase + (ch & 1) * STAGE_BYTES;
        const uint32_t sAh = st + 0 * ARR_BYTES;
        const uint32_t sAl = st + 1 * ARR_BYTES;
        const uint32_t sBh = st + 2 * ARR_BYTES;
        const uint32_t sBl = st + 3 * ARR_BYTES;

        #pragma unroll
        for (int kk = 0; kk < 2; kk++) {
            const uint32_t kb = kk * 32 + acolb;
            uint32_t ah[4][4], al[4][4], bh[4][2], bl[4][2];
            #pragma unroll
            for (int mt = 0; mt < 4; mt++) {
                const uint32_t ro = (uint32_t)((warp_m * 64 + mt * 16 + arow) * (LDA * 2)) + kb;
                ldmx4(sAh + ro, ah[mt][0], ah[mt][1], ah[mt][2], ah[mt][3]);
                ldmx4(sAl + ro, al[mt][0], al[mt][1], al[mt][2], al[mt][3]);
            }
            #pragma unroll
            for (int pr = 0; pr < 2; pr++) {
                const uint32_t ro = (uint32_t)((warp_n * 32 + pr * 16 + arow) * (LDA * 2)) + kb;
                uint32_t r0, r1, r2, r3;
                ldmx4(sBh + ro, r0, r1, r2, r3);
                bh[2*pr][0] = r0; bh[2*pr][1] = r2; bh[2*pr+1][0] = r1; bh[2*pr+1][1] = r3;
                ldmx4(sBl + ro, r0, r1, r2, r3);
                bl[2*pr][0] = r0; bl[2*pr][1] = r2; bl[2*pr+1][0] = r1; bl[2*pr+1][1] = r3;
            }
            #pragma unroll
            for (int mt = 0; mt < 4; mt++)
                #pragma unroll
                for (int nt = 0; nt < 4; nt++) {
                    mma_bf16(c[mt][nt], ah[mt], bh[nt]);
                    mma_bf16(c[mt][nt], al[mt], bh[nt]);
                    mma_bf16(c[mt][nt], ah[mt], bl[nt]);
                }
        }
        __syncthreads();
    }

    // ---- epilogue ----
    const int qrow = lane >> 2;            // 0..7
    const int qcol = (lane & 3) * 2;       // 0,2,4,6

    #pragma unroll
    for (int mt = 0; mt < 4; mt++) {
        const int rA = m0 + warp_m * 64 + mt * 16 + qrow;
        const int rB = rA + 8;

        float a2A[12], a2B[12];
        for (int k = 0; k < K2; k++) {
            a2A[k] = __ldg(A2 + (size_t)rA * K2 + k);
            a2B[k] = __ldg(A2 + (size_t)rB * K2 + k);
        }

        #pragma unroll
        for (int nt = 0; nt < 4; nt++) {
            const int colg = n0 + warp_n * 32 + nt * 8 + qcol;
            const float b0 = __ldg(bias + colg), b1 = __ldg(bias + colg + 1);
            float v0 = c[mt][nt][0] + b0, v1 = c[mt][nt][1] + b1;
            float v2 = c[mt][nt][2] + b0, v3 = c[mt][nt][3] + b1;

            for (int k = 0; k < K2; k++) {
                const float w0 = __ldg(Wtail + (size_t)k * FD + colg);
                const float w1 = __ldg(Wtail + (size_t)k * FD + colg + 1);
                v0 += a2A[k] * w0; v1 += a2A[k] * w1;
                v2 += a2B[k] * w0; v3 += a2B[k] * w1;
            }
            if (addres) {
                float2 hA = __bfloat1622float2(*(const __nv_bfloat162*)(Ahi + (size_t)rA * FD + colg));
                float2 lA = __bfloat1622float2(*(const __nv_bfloat162*)(Alo + (size_t)rA * FD + colg));
                float2 hB = __bfloat1622float2(*(const __nv_bfloat162*)(Ahi + (size_t)rB * FD + colg));
                float2 lB = __bfloat1622float2(*(const __nv_bfloat162*)(Alo + (size_t)rB * FD + colg));
                v0 += hA.x + lA.x; v1 += hA.y + lA.y;
                v2 += hB.x + lB.x; v3 += hB.y + lB.y;
            }
            v0 = fmaxf(v0, 0.0f); v1 = fmaxf(v1, 0.0f);
            v2 = fmaxf(v2, 0.0f); v3 = fmaxf(v3, 0.0f);

            if (outF) {
                *(float2*)(outF + (size_t)rA * FD + colg) = make_float2(v0, v1);
                *(float2*)(outF + (size_t)rB * FD + colg) = make_float2(v2, v3);
            } else {
                __nv_bfloat16 h0,h1,h2,h3,l0,l1,l2,l3;
                split2(v0,h0,l0); split2(v1,h1,l1);
                split2(v2,h2,l2); split2(v3,h3,l3);
                *(__nv_bfloat162*)(outHi + (size_t)rA * FD + colg) = __nv_bfloat162(h0, h1);
                *(__nv_bfloat162*)(outLo + (size_t)rA * FD + colg) = __nv_bfloat162(l0, l1);
                *(__nv_bfloat162*)(outHi + (size_t)rB * FD + colg) = __nv_bfloat162(h2, h3);
                *(__nv_bfloat162*)(outLo + (size_t)rB * FD + colg) = __nv_bfloat162(l2, l3);
            }
        }
    }
}

// ---------------------------------------------------------------------------
// Row dot with w2 (+b2) + cross-stage accumulation
// ---------------------------------------------------------------------------
__global__ __launch_bounds__(256) void rowdot_kernel(
    const float* __restrict__ H, const float* __restrict__ w2,
    const float* __restrict__ b2, const float* __restrict__ prev,
    float* __restrict__ out)
{
    const int warp = threadIdx.x >> 5;
    const int lane = threadIdx.x & 31;
    const int row = blockIdx.x * 8 + warp;
    const float4* hp = (const float4*)(H + (size_t)row * FD);
    const float4* wp = (const float4*)w2;
    float s = 0.0f;
    #pragma unroll
    for (int q = 0; q < 4; q++) {
        const float4 h4 = hp[lane + 32 * q];
        const float4 w4 = wp[lane + 32 * q];
        s += h4.x * w4.x + h4.y * w4.y + h4.z * w4.z + h4.w * w4.w;
    }
    #pragma unroll
    for (int o = 16; o; o >>= 1) s += __shfl_xor_sync(0xFFFFFFFFu, s, o);
    if (lane == 0) out[row] = (prev ? prev[row] : 0.0f) + s + b2[0];
}

// ---------------------------------------------------------------------------
// Host orchestration
// ---------------------------------------------------------------------------
extern "C" void kernel_launch(void* const* d_in, const int* in_sizes, int n_in,
                              void* d_out, int out_size)
{
    const float* latent = (const float*)d_in[0];
    const float* rp     = (const float*)d_in[1];
    const float* w1[3] = {(const float*)d_in[2],  (const float*)d_in[8],  (const float*)d_in[14]};
    const float* b1[3] = {(const float*)d_in[3],  (const float*)d_in[9],  (const float*)d_in[15]};
    const float* wr[3] = {(const float*)d_in[4],  (const float*)d_in[10], (const float*)d_in[16]};
    const float* br[3] = {(const float*)d_in[5],  (const float*)d_in[11], (const float*)d_in[17]};
    const float* w2[3] = {(const float*)d_in[6],  (const float*)d_in[12], (const float*)d_in[18]};
    const float* b2[3] = {(const float*)d_in[7],  (const float*)d_in[13], (const float*)d_in[19]};

    float *feat, *h2, *std1, *std2;
    __nv_bfloat16 *lat_hi, *lat_lo, *h_hi, *h_lo, *w1T_hi, *w1T_lo, *wrT_hi, *wrT_lo;
    cudaGetSymbolAddress((void**)&feat,   g_feat);
    cudaGetSymbolAddress((void**)&lat_hi, g_lat_hi);
    cudaGetSymbolAddress((void**)&lat_lo, g_lat_lo);
    cudaGetSymbolAddress((void**)&h_hi,   g_h_hi);
    cudaGetSymbolAddress((void**)&h_lo,   g_h_lo);
    cudaGetSymbolAddress((void**)&h2,     g_h2);
    cudaGetSymbolAddress((void**)&std1,   g_std1);
    cudaGetSymbolAddress((void**)&std2,   g_std2);
    cudaGetSymbolAddress((void**)&w1T_hi, g_w1T_hi);
    cudaGetSymbolAddress((void**)&w1T_lo, g_w1T_lo);
    cudaGetSymbolAddress((void**)&wrT_hi, g_wrT_hi);
    cudaGetSymbolAddress((void**)&wrT_lo, g_wrT_lo);

    float* out = (float*)d_out;

    static bool attr_set = false;
    cudaFuncSetAttribute(gemm_mma_kernel, cudaFuncAttributeMaxDynamicSharedMemorySize, SMEM_TOTAL);
    (void)attr_set;

    const dim3 ggrid(FD / BN, MROWS / BM);   // (4, 256)
    const dim3 tgrid(16, 16);
    const int  rd_blocks = MROWS / 8;

    conv_split_kernel<<<2048, 256>>>(latent, lat_hi, lat_lo, MROWS * FD / 4);
    knn_feat_kernel<<<dim3(NPTS / 256, BATCH), 256>>>(rp, feat);

    const float* stdprev[3] = {nullptr, std1, std2};
    const float* a2s[3]     = {feat, std1, std2};
    const int    k2s[3]     = {12, 1, 1};
    float*       stdout_[3] = {std1, std2, out};

    for (int s = 0; s < 3; s++) {
        transW_kernel<<<tgrid, 256>>>(w1[s], w1T_hi, w1T_lo);
        gemm_mma_kernel<<<ggrid, 256, SMEM_TOTAL>>>(
            lat_hi, lat_lo, w1T_hi, w1T_lo, b1[s],
            a2s[s], k2s[s], w1[s] + (size_t)FD * FD, 0,
            nullptr, h_hi, h_lo);
        transW_kernel<<<tgrid, 256>>>(wr[s], wrT_hi, wrT_lo);
        gemm_mma_kernel<<<ggrid, 256, SMEM_TOTAL>>>(
            h_hi, h_lo, wrT_hi, wrT_lo, br[s],
            nullptr, 0, nullptr, 1,
            h2, nullptr, nullptr);
        rowdot_kernel<<<rd_blocks, 256>>>(h2, w2[s], b2[s], stdprev[s], stdout_[s]);
    }
}